// round 13
// baseline (speedup 1.0000x reference)
#include <cuda_runtime.h>
#include <cuda_bf16.h>
#include <cstdint>

#define NN      100000
#define NNP     100096          // padded to 782*128 rows
#define NE      1200000
#define DIM     64
#define NG      128
#define NL      5
#define NBLK    98              // ceil(NN/1024)

// Persistent scratch (device globals — no allocation). Zero-init at load.
// Pad rows [NN, NNP) of g_z are never written -> stay 0 -> deterministic.
__device__ float g_hA[NNP * DIM];
__device__ float g_hB[NNP * DIM];
__device__ float g_z[NNP * DIM];
__device__ float g_pool[NG * DIM];
__device__ int   g_cnt[NN];
__device__ int   g_off[NN + 1];
__device__ int   g_bsum[128];
__device__ int   g_ssrc[NE];
// Prepped weights: [layer][{W1hi,W1lo,W2hi,W2lo}][n*64+k]  (transposed, BN-folded)
__device__ __nv_bfloat16 g_wb[NL][4][DIM * DIM];
__device__ float         g_bias[NL][2][DIM];

// ---------------------------------------------------------------------------
// warp-MMA helpers (sm_80+ instructions; valid on plain sm_100 target)
// ---------------------------------------------------------------------------
__device__ __forceinline__ uint32_t smem_u32(const void* p) {
    uint32_t a;
    asm("{ .reg .u64 t; cvta.to.shared.u64 t, %1; cvt.u32.u64 %0, t; }"
        : "=r"(a) : "l"(p));
    return a;
}
__device__ __forceinline__ void ldm4(uint32_t* r, uint32_t addr) {
    asm volatile("ldmatrix.sync.aligned.m8n8.x4.shared.b16 {%0,%1,%2,%3}, [%4];"
                 : "=r"(r[0]), "=r"(r[1]), "=r"(r[2]), "=r"(r[3]) : "r"(addr));
}
__device__ __forceinline__ void mma_bf16(float* d, const uint32_t* a,
                                         uint32_t b0, uint32_t b1) {
    asm volatile("mma.sync.aligned.m16n8k16.row.col.f32.bf16.bf16.f32 "
                 "{%0,%1,%2,%3}, {%4,%5,%6,%7}, {%8,%9}, {%0,%1,%2,%3};"
                 : "+f"(d[0]), "+f"(d[1]), "+f"(d[2]), "+f"(d[3])
                 : "r"(a[0]), "r"(a[1]), "r"(a[2]), "r"(a[3]), "r"(b0), "r"(b1));
}
__device__ __forceinline__ uint32_t pbf2(__nv_bfloat16 a, __nv_bfloat16 b) {
    __nv_bfloat162 t(a, b);
    return *reinterpret_cast<uint32_t*>(&t);
}

// ---------------------------------------------------------------------------
// Counting sort of edges by dst (CSR build; edge_index constant per launch).
// ---------------------------------------------------------------------------
__global__ void zero_cnt_kernel() {
    int i = blockIdx.x * blockDim.x + threadIdx.x;
    if (i < NN) g_cnt[i] = 0;
}
__global__ void hist_kernel(const int* __restrict__ ei) {
    int e = blockIdx.x * blockDim.x + threadIdx.x;
    if (e < NE) atomicAdd(&g_cnt[__ldg(ei + NE + e)], 1);
}

// Phase 1: per-block exclusive scan of 1024 elements + block total.
__global__ __launch_bounds__(1024)
void scan1_kernel() {
    __shared__ int sh[1024];
    const int t = threadIdx.x;
    const int i = blockIdx.x * 1024 + t;
    int v = (i < NN) ? g_cnt[i] : 0;
    sh[t] = v;
    __syncthreads();
    #pragma unroll
    for (int off = 1; off < 1024; off <<= 1) {
        int u = (t >= off) ? sh[t - off] : 0;
        __syncthreads();
        sh[t] += u;
        __syncthreads();
    }
    if (i < NN) g_off[i] = sh[t] - v;              // exclusive within block
    if (t == 1023) g_bsum[blockIdx.x] = sh[1023];  // block total
}

// Phase 2: exclusive scan of the 98 block totals (one small block).
__global__ __launch_bounds__(128)
void scan2_kernel() {
    __shared__ int sh[128];
    const int t = threadIdx.x;
    int v = (t < NBLK) ? g_bsum[t] : 0;
    sh[t] = v;
    __syncthreads();
    #pragma unroll
    for (int off = 1; off < 128; off <<= 1) {
        int u = (t >= off) ? sh[t - off] : 0;
        __syncthreads();
        sh[t] += u;
        __syncthreads();
    }
    if (t < NBLK) g_bsum[t] = sh[t] - v;
}

// Phase 3: add block offsets, mirror into fill cursor, close the CSR.
__global__ void scan3_kernel() {
    int i = blockIdx.x * blockDim.x + threadIdx.x;
    if (i < NN) {
        int o = g_off[i] + g_bsum[i >> 10];
        g_off[i] = o;
        g_cnt[i] = o;        // reuse as fill cursor
    }
    if (i == 0) g_off[NN] = NE;
}

__global__ void fill_kernel(const int* __restrict__ ei) {
    int e = blockIdx.x * blockDim.x + threadIdx.x;
    if (e >= NE) return;
    int d = __ldg(ei + NE + e);
    int pos = atomicAdd(&g_cnt[d], 1);
    g_ssrc[pos] = __ldg(ei + e);
}

// ---------------------------------------------------------------------------
// Weight prep: fold BN into W1/b1, transpose to [n][k], bf16 hi/lo split.
// ---------------------------------------------------------------------------
__global__ __launch_bounds__(128)
void prep_kernel(const float* __restrict__ W1s, const float* __restrict__ b1s,
                 const float* __restrict__ gam, const float* __restrict__ bet,
                 const float* __restrict__ W2s, const float* __restrict__ b2s)
{
    const int l = blockIdx.x;
    const int tid = threadIdx.x;
    const float bns = rsqrtf(1.0f + 1e-5f);
    for (int i = tid; i < DIM * DIM; i += 128) {
        int k = i >> 6, n = i & 63;
        float w1 = W1s[l * DIM * DIM + i] * (gam[l * DIM + n] * bns);
        __nv_bfloat16 h1 = __float2bfloat16(w1);
        __nv_bfloat16 l1 = __float2bfloat16(w1 - __bfloat162float(h1));
        g_wb[l][0][n * DIM + k] = h1;
        g_wb[l][1][n * DIM + k] = l1;
        float w2 = W2s[l * DIM * DIM + i];
        __nv_bfloat16 h2 = __float2bfloat16(w2);
        __nv_bfloat16 l2 = __float2bfloat16(w2 - __bfloat162float(h2));
        g_wb[l][2][n * DIM + k] = h2;
        g_wb[l][3][n * DIM + k] = l2;
    }
    if (tid < DIM) {
        g_bias[l][0][tid] = b1s[l * DIM + tid] * (gam[l * DIM + tid] * bns) + bet[l * DIM + tid];
        g_bias[l][1][tid] = b2s[l * DIM + tid];
    }
}

// ---------------------------------------------------------------------------
// Gather aggregate (atomic-free): z[i] = h[i] + sum_{j in N(i)} h[j]
// 16 lanes per node (float4 each), 16 nodes per 256-thread block.
// ---------------------------------------------------------------------------
__global__ __launch_bounds__(256)
void gather_kernel(const float* __restrict__ h, float* __restrict__ z)
{
    const int tid  = threadIdx.x;
    const int lane = tid & 15;
    const int node = blockIdx.x * 16 + (tid >> 4);
    if (node >= NN) return;

    float4 acc = *reinterpret_cast<const float4*>(h + (size_t)node * DIM + lane * 4);
    const int e0 = g_off[node];
    const int e1 = g_off[node + 1];
    for (int e = e0; e < e1; e++) {
        int s = __ldg(&g_ssrc[e]);
        float4 v = *reinterpret_cast<const float4*>(h + (size_t)s * DIM + lane * 4);
        acc.x += v.x; acc.y += v.y; acc.z += v.z; acc.w += v.w;
    }
    *reinterpret_cast<float4*>(z + (size_t)node * DIM + lane * 4) = acc;
}

// ---------------------------------------------------------------------------
// Tensor-core MLP via mma.sync bf16 (3-term split, fp32 accum):
//   GEMM1: y = relu((z@W1')+b1'); y written back into the A tiles (own rows)
//   GEMM2: h = relu((y@W2)+b2) -> gmem fp32
// 256 threads (8 warps, 16 rows/warp) for 2x latency hiding at same smem.
// W OVERLAY: one hi/lo weight pair resident at a time -> 55,808 B -> 4 CTAs/SM
// -> 32 warps/SM during mlp.
// ---------------------------------------------------------------------------
#define STR     72                          // bf16 stride (144 B): ldmatrix conflict-free
#define SM_BIAS 0                           // 128 floats = 512 B
#define SM_A0   512                         // 128*72*2 = 18432
#define SM_A1   (SM_A0 + 128 * STR * 2)     // 18944
#define SM_W    (SM_A1 + 128 * STR * 2)     // 37376; 2 tiles x 64*72*2 (=9216)
#define SMEM_MM (SM_W + 2 * 64 * STR * 2)   // 55808 B

__global__ __launch_bounds__(256)
void mlp_mma_kernel(const float* __restrict__ z_in,
                    const __nv_bfloat16* __restrict__ wsp,   // [4][64*64] as [n][k]
                    const float* __restrict__ bias,          // [2][64]
                    float* __restrict__ hout)
{
    extern __shared__ char smem[];
    const uint32_t sb = smem_u32(smem);
    const int tid = threadIdx.x, wid = tid >> 5, lane = tid & 31;

    // --- load W1 hi/lo pair: [n][k] compact -> padded stride-72 tiles ---
    const uint32_t* wsrc = reinterpret_cast<const uint32_t*>(wsp);
    for (int i = tid; i < 4096; i += 256) {
        int tile = i >> 11;                        // 0=hi, 1=lo
        int rem  = i & 2047;
        int n = rem >> 5, k2 = rem & 31;           // k2: pair index (2 bf16 per u32)
        *reinterpret_cast<uint32_t*>(smem + SM_W + tile * 9216 + n * 144 + k2 * 4) = wsrc[i];
    }
    if (tid < 128) reinterpret_cast<float*>(smem + SM_BIAS)[tid] = bias[tid];

    // --- load z rows, split to bf16 hi/lo ---
    {
        const float4* zp = reinterpret_cast<const float4*>(z_in + (size_t)blockIdx.x * 128 * DIM);
        for (int i = tid; i < 2048; i += 256) {
            int row = i >> 4, q = i & 15;          // cols 4q..4q+3
            float4 v = zp[i];
            __nv_bfloat16 h0 = __float2bfloat16(v.x), h1 = __float2bfloat16(v.y);
            __nv_bfloat16 h2 = __float2bfloat16(v.z), h3 = __float2bfloat16(v.w);
            __nv_bfloat16 l0 = __float2bfloat16(v.x - __bfloat162float(h0));
            __nv_bfloat16 l1 = __float2bfloat16(v.y - __bfloat162float(h1));
            __nv_bfloat16 l2 = __float2bfloat16(v.z - __bfloat162float(h2));
            __nv_bfloat16 l3 = __float2bfloat16(v.w - __bfloat162float(h3));
            char* d0 = smem + SM_A0 + row * 144 + q * 8;
            char* d1 = smem + SM_A1 + row * 144 + q * 8;
            *reinterpret_cast<uint32_t*>(d0)     = pbf2(h0, h1);
            *reinterpret_cast<uint32_t*>(d0 + 4) = pbf2(h2, h3);
            *reinterpret_cast<uint32_t*>(d1)     = pbf2(l0, l1);
            *reinterpret_cast<uint32_t*>(d1 + 4) = pbf2(l2, l3);
        }
    }
    __syncthreads();
    const float* sbias = reinterpret_cast<const float*>(smem + SM_BIAS);

    const int g  = lane >> 3;        // ldmatrix address group 0..3
    const int ri = lane & 7;
    const int wrow = wid * 16;       // this warp's row base within CTA tile (16 rows)

    float acc[8][4];

    #pragma unroll
    for (int gemm = 0; gemm < 2; gemm++) {
        const uint32_t wbase = sb + SM_W;                         // hi tile (overlaid)
        // init accumulators with bias
        #pragma unroll
        for (int nt = 0; nt < 8; nt++) {
            int c = nt * 8 + (lane & 3) * 2;
            float b0 = sbias[gemm * 64 + c], b1v = sbias[gemm * 64 + c + 1];
            acc[nt][0] = b0; acc[nt][1] = b1v;
            acc[nt][2] = b0; acc[nt][3] = b1v;
        }

        #pragma unroll
        for (int k = 0; k < 4; k++) {
            const int K = k * 16;
            uint32_t ah[4], al[4];
            {
                uint32_t ao = (uint32_t)((wrow + (g & 1) * 8 + ri) * 144
                                         + (K + (g >> 1) * 8) * 2);
                ldm4(ah, sb + SM_A0 + ao);
                ldm4(al, sb + SM_A1 + ao);
            }
            #pragma unroll
            for (int np = 0; np < 4; np++) {
                uint32_t bo = (uint32_t)((np * 16 + (g >> 1) * 8 + ri) * 144
                                         + (K + (g & 1) * 8) * 2);
                uint32_t bh[4], bl[4];
                ldm4(bh, wbase + bo);
                ldm4(bl, wbase + 9216 + bo);
                #pragma unroll
                for (int h2 = 0; h2 < 2; h2++) {
                    int nt = np * 2 + h2;
                    mma_bf16(acc[nt], ah, bh[2 * h2], bh[2 * h2 + 1]);
                    mma_bf16(acc[nt], ah, bl[2 * h2], bl[2 * h2 + 1]);
                    mma_bf16(acc[nt], al, bh[2 * h2], bh[2 * h2 + 1]);
                }
            }
        }

        if (gemm == 0) {
            // epilogue1: relu, hi/lo split, write back into OWN rows of A tiles
            #pragma unroll
            for (int nt = 0; nt < 8; nt++) {
                int row0 = wrow + (lane >> 2);
                int col  = nt * 8 + (lane & 3) * 2;
                float v0 = fmaxf(acc[nt][0], 0.0f);
                float v1 = fmaxf(acc[nt][1], 0.0f);
                float v2 = fmaxf(acc[nt][2], 0.0f);
                float v3 = fmaxf(acc[nt][3], 0.0f);
                __nv_bfloat16 h0 = __float2bfloat16(v0), h1 = __float2bfloat16(v1);
                __nv_bfloat16 h2 = __float2bfloat16(v2), h3 = __float2bfloat16(v3);
                __nv_bfloat16 e0 = __float2bfloat16(v0 - __bfloat162float(h0));
                __nv_bfloat16 e1 = __float2bfloat16(v1 - __bfloat162float(h1));
                __nv_bfloat16 e2 = __float2bfloat16(v2 - __bfloat162float(h2));
                __nv_bfloat16 e3 = __float2bfloat16(v3 - __bfloat162float(h3));
                uint32_t o0 = (uint32_t)(row0 * 144 + col * 2);
                uint32_t o1 = (uint32_t)((row0 + 8) * 144 + col * 2);
                *reinterpret_cast<uint32_t*>(smem + SM_A0 + o0) = pbf2(h0, h1);
                *reinterpret_cast<uint32_t*>(smem + SM_A0 + o1) = pbf2(h2, h3);
                *reinterpret_cast<uint32_t*>(smem + SM_A1 + o0) = pbf2(e0, e1);
                *reinterpret_cast<uint32_t*>(smem + SM_A1 + o1) = pbf2(e2, e3);
            }
            __syncthreads();          // all warps done reading W1 tiles
            // overlay: load W2 hi/lo pair into the same slab
            for (int i = tid; i < 4096; i += 256) {
                int tile = i >> 11;
                int rem  = i & 2047;
                int n = rem >> 5, k2 = rem & 31;
                *reinterpret_cast<uint32_t*>(smem + SM_W + tile * 9216 + n * 144 + k2 * 4)
                    = wsrc[4096 + i];
            }
            __syncthreads();          // W2 visible (also covers A-tile writes)
        }
    }

    // epilogue2: relu -> gmem fp32
    {
        const size_t rbase = (size_t)blockIdx.x * 128 + wrow;
        #pragma unroll
        for (int nt = 0; nt < 8; nt++) {
            size_t row0 = rbase + (lane >> 2);
            int col = nt * 8 + (lane & 3) * 2;
            float2 v01 = make_float2(fmaxf(acc[nt][0], 0.0f),
                                     fmaxf(acc[nt][1], 0.0f));
            float2 v23 = make_float2(fmaxf(acc[nt][2], 0.0f),
                                     fmaxf(acc[nt][3], 0.0f));
            *reinterpret_cast<float2*>(hout + row0 * DIM + col)       = v01;
            *reinterpret_cast<float2*>(hout + (row0 + 8) * DIM + col) = v23;
        }
    }
}

// ---------------------------------------------------------------------------
// Global add pool (batch sorted): running segment sums, REDG flush on change.
// ---------------------------------------------------------------------------
__global__ __launch_bounds__(256)
void pool_kernel(const float* __restrict__ h,
                 const int*   __restrict__ batch,
                 float*       __restrict__ pl)
{
    const int tid  = threadIdx.x;
    const int lane = tid & 15;
    const int sub  = tid >> 4;
    const int base = blockIdx.x * 1024;

    float4 acc = make_float4(0.f, 0.f, 0.f, 0.f);
    int cur = -1;
    for (int i = 0; i < 64; i++) {
        int n = base + sub + i * 16;
        if (n >= NN) break;
        int g = __ldg(batch + n);
        if (g != cur) {
            if (cur >= 0) {
                float4* a = reinterpret_cast<float4*>(pl + (size_t)cur * DIM + lane * 4);
                asm volatile("red.global.add.v4.f32 [%0], {%1,%2,%3,%4};"
                             :: "l"(a), "f"(acc.x), "f"(acc.y), "f"(acc.z), "f"(acc.w)
                             : "memory");
            }
            cur = g;
            acc = make_float4(0.f, 0.f, 0.f, 0.f);
        }
        float4 v = *reinterpret_cast<const float4*>(h + (size_t)n * DIM + lane * 4);
        acc.x += v.x; acc.y += v.y; acc.z += v.z; acc.w += v.w;
    }
    if (cur >= 0) {
        float4* a = reinterpret_cast<float4*>(pl + (size_t)cur * DIM + lane * 4);
        asm volatile("red.global.add.v4.f32 [%0], {%1,%2,%3,%4};"
                     :: "l"(a), "f"(acc.x), "f"(acc.y), "f"(acc.z), "f"(acc.w)
                     : "memory");
    }
}

// ---------------------------------------------------------------------------
// Final: out = relu(pool @ lin1_w + lin1_b). Zeroes pool after reading.
// ---------------------------------------------------------------------------
__global__ __launch_bounds__(128)
void final_kernel(float*       __restrict__ pl,
                  const float* __restrict__ W,
                  const float* __restrict__ b,
                  float*       __restrict__ out)
{
    extern __shared__ float fsm[];
    float* sW = fsm;              // 4096 floats
    float* sb2 = sW + DIM * DIM;  // 64
    float* sx = sb2 + DIM;        // 64 * 128

    const int tid = threadIdx.x;
    for (int i = tid; i < DIM * DIM; i += 128) sW[i] = W[i];
    if (tid < DIM) sb2[tid] = b[tid];

    float4* pp = reinterpret_cast<float4*>(pl + (size_t)tid * DIM);
    #pragma unroll
    for (int k4 = 0; k4 < 16; k4++) {
        float4 v = pp[k4];
        sx[(4 * k4 + 0) * 128 + tid] = v.x;
        sx[(4 * k4 + 1) * 128 + tid] = v.y;
        sx[(4 * k4 + 2) * 128 + tid] = v.z;
        sx[(4 * k4 + 3) * 128 + tid] = v.w;
        pp[k4] = make_float4(0.f, 0.f, 0.f, 0.f);   // keep pool zeroed
    }
    __syncthreads();

    float acc[DIM];
    #pragma unroll
    for (int j = 0; j < DIM; j++) acc[j] = sb2[j];
    for (int k = 0; k < DIM; k++) {
        float xk = sx[k * 128 + tid];
        #pragma unroll
        for (int j = 0; j < DIM; j += 4) {
            float4 w = *reinterpret_cast<const float4*>(&sW[k * DIM + j]);
            acc[j + 0] += xk * w.x;
            acc[j + 1] += xk * w.y;
            acc[j + 2] += xk * w.z;
            acc[j + 3] += xk * w.w;
        }
    }
    float* op = out + (size_t)tid * DIM;
    #pragma unroll
    for (int j = 0; j < DIM; j++) op[j] = fmaxf(acc[j], 0.0f);
}

// ---------------------------------------------------------------------------
extern "C" void kernel_launch(void* const* d_in, const int* in_sizes, int n_in,
                              void* d_out, int out_size)
{
    const float* x      = (const float*)d_in[0];
    const int*   ei     = (const int*)  d_in[1];
    const int*   batch  = (const int*)  d_in[2];
    const float* W1s    = (const float*)d_in[3];
    const float* b1s    = (const float*)d_in[4];
    const float* gammas = (const float*)d_in[5];
    const float* betas  = (const float*)d_in[6];
    const float* W2s    = (const float*)d_in[7];
    const float* b2s    = (const float*)d_in[8];
    const float* lw     = (const float*)d_in[9];
    const float* lb     = (const float*)d_in[10];
    float* out = (float*)d_out;

    float *hA, *hB, *zb, *pl;
    __nv_bfloat16* wb;
    float* bs;
    cudaGetSymbolAddress((void**)&hA, g_hA);
    cudaGetSymbolAddress((void**)&hB, g_hB);
    cudaGetSymbolAddress((void**)&zb, g_z);
    cudaGetSymbolAddress((void**)&pl, g_pool);
    cudaGetSymbolAddress((void**)&wb, g_wb);
    cudaGetSymbolAddress((void**)&bs, g_bias);

    const int final_smem = (DIM * DIM + DIM + DIM * 128) * (int)sizeof(float);
    cudaFuncSetAttribute(mlp_mma_kernel, cudaFuncAttributeMaxDynamicSharedMemorySize, SMEM_MM);
    cudaFuncSetAttribute(final_kernel,   cudaFuncAttributeMaxDynamicSharedMemorySize, final_smem);

    // CSR build + weight prep (independent)
    zero_cnt_kernel<<<(NN + 255) / 256, 256>>>();
    prep_kernel<<<NL, 128>>>(W1s, b1s, gammas, betas, W2s, b2s);
    hist_kernel<<<(NE + 255) / 256, 256>>>(ei);
    scan1_kernel<<<NBLK, 1024>>>();
    scan2_kernel<<<1, 128>>>();
    scan3_kernel<<<(NN + 255) / 256, 256>>>();
    fill_kernel<<<(NE + 255) / 256, 256>>>(ei);

    const int gat_blocks = (NN + 15) / 16;     // 6250
    const int mlp_blocks = NNP / 128;          // 782

    const float* hcur = x;
    float*       hnxt = hA;
    for (int l = 0; l < NL; l++) {
        gather_kernel<<<gat_blocks, 256>>>(hcur, zb);
        mlp_mma_kernel<<<mlp_blocks, 256, SMEM_MM>>>(zb,
                                                     wb + (size_t)l * 4 * DIM * DIM,
                                                     bs + (size_t)l * 2 * DIM,
                                                     hnxt);
        hcur = hnxt;
        hnxt = (hcur == hA) ? hB : hA;
    }

    pool_kernel<<<(NN + 1023) / 1024, 256>>>(hcur, batch, pl);
    final_kernel<<<1, 128, final_smem>>>(pl, lw, lb, out);
}

// round 15
// speedup vs baseline: 1.1337x; 1.1337x over previous
#include <cuda_runtime.h>
#include <cuda_bf16.h>
#include <cstdint>

#define NN      100000
#define NNP     100096          // padded to 782*128 rows
#define NE      1200000
#define DIM     64
#define NG      128
#define NL      5
#define NBLK    98              // ceil(NN/1024)

// Persistent scratch (device globals — no allocation). Zero-init at load.
// Invariants: g_pool zeroed by final_kernel; g_cnt zeroed by pool_kernel;
// pad rows [NN,NNP) of g_zhi/g_zlo never written -> stay 0.
__device__ float    g_hA[NNP * DIM];
__device__ float    g_hB[NNP * DIM];
__device__ uint32_t g_zhi[NNP * 32];   // z hi bf16 pairs, 32 u32 per row
__device__ uint32_t g_zlo[NNP * 32];   // z lo bf16 pairs
__device__ float    g_pool[NG * DIM];
__device__ int      g_cnt[NN];
__device__ int      g_off[NN + 1];
__device__ int      g_bsum[128];
__device__ int      g_ssrc[NE];
// Pre-padded weight tiles: [layer][{W1hi,W1lo,W2hi,W2lo}][64 rows x 36 u32]
// (row stride 144 B = ldmatrix-friendly; padding u32s stay 0)
__device__ uint32_t g_wbp[NL][4][64 * 36];
__device__ float    g_bias[NL][2][DIM];

// ---------------------------------------------------------------------------
// warp-MMA helpers (sm_80+ instructions; valid on plain sm_100 target)
// ---------------------------------------------------------------------------
__device__ __forceinline__ uint32_t smem_u32(const void* p) {
    uint32_t a;
    asm("{ .reg .u64 t; cvta.to.shared.u64 t, %1; cvt.u32.u64 %0, t; }"
        : "=r"(a) : "l"(p));
    return a;
}
__device__ __forceinline__ void ldm4(uint32_t* r, uint32_t addr) {
    asm volatile("ldmatrix.sync.aligned.m8n8.x4.shared.b16 {%0,%1,%2,%3}, [%4];"
                 : "=r"(r[0]), "=r"(r[1]), "=r"(r[2]), "=r"(r[3]) : "r"(addr));
}
__device__ __forceinline__ void mma_bf16(float* d, const uint32_t* a,
                                         uint32_t b0, uint32_t b1) {
    asm volatile("mma.sync.aligned.m16n8k16.row.col.f32.bf16.bf16.f32 "
                 "{%0,%1,%2,%3}, {%4,%5,%6,%7}, {%8,%9}, {%0,%1,%2,%3};"
                 : "+f"(d[0]), "+f"(d[1]), "+f"(d[2]), "+f"(d[3])
                 : "r"(a[0]), "r"(a[1]), "r"(a[2]), "r"(a[3]), "r"(b0), "r"(b1));
}
__device__ __forceinline__ uint32_t pbf2(__nv_bfloat16 a, __nv_bfloat16 b) {
    __nv_bfloat162 t(a, b);
    return *reinterpret_cast<uint32_t*>(&t);
}

// ---------------------------------------------------------------------------
// Counting sort of edges by dst (CSR build; edge_index constant per launch).
// g_cnt arrives zeroed (load-time init / previous call's pool_kernel).
// ---------------------------------------------------------------------------
__global__ void hist_kernel(const int* __restrict__ ei) {
    int e = blockIdx.x * blockDim.x + threadIdx.x;
    if (e < NE) atomicAdd(&g_cnt[__ldg(ei + NE + e)], 1);
}

// Phase 1: per-block exclusive scan of 1024 elements + block total.
__global__ __launch_bounds__(1024)
void scan1_kernel() {
    __shared__ int sh[1024];
    const int t = threadIdx.x;
    const int i = blockIdx.x * 1024 + t;
    int v = (i < NN) ? g_cnt[i] : 0;
    sh[t] = v;
    __syncthreads();
    #pragma unroll
    for (int off = 1; off < 1024; off <<= 1) {
        int u = (t >= off) ? sh[t - off] : 0;
        __syncthreads();
        sh[t] += u;
        __syncthreads();
    }
    if (i < NN) g_off[i] = sh[t] - v;              // exclusive within block
    if (t == 1023) g_bsum[blockIdx.x] = sh[1023];  // block total
}

// Phase 2: exclusive scan of the 98 block totals (one small block).
__global__ __launch_bounds__(128)
void scan2_kernel() {
    __shared__ int sh[128];
    const int t = threadIdx.x;
    int v = (t < NBLK) ? g_bsum[t] : 0;
    sh[t] = v;
    __syncthreads();
    #pragma unroll
    for (int off = 1; off < 128; off <<= 1) {
        int u = (t >= off) ? sh[t - off] : 0;
        __syncthreads();
        sh[t] += u;
        __syncthreads();
    }
    if (t < NBLK) g_bsum[t] = sh[t] - v;
}

// Phase 3: add block offsets, mirror into fill cursor, close the CSR.
__global__ void scan3_kernel() {
    int i = blockIdx.x * blockDim.x + threadIdx.x;
    if (i < NN) {
        int o = g_off[i] + g_bsum[i >> 10];
        g_off[i] = o;
        g_cnt[i] = o;        // reuse as fill cursor
    }
    if (i == 0) g_off[NN] = NE;
}

__global__ void fill_kernel(const int* __restrict__ ei) {
    int e = blockIdx.x * blockDim.x + threadIdx.x;
    if (e >= NE) return;
    int d = __ldg(ei + NE + e);
    int pos = atomicAdd(&g_cnt[d], 1);
    g_ssrc[pos] = __ldg(ei + e);
}

// ---------------------------------------------------------------------------
// Weight prep: fold BN into W1/b1, transpose to [n][k], bf16 hi/lo split,
// write PRE-PADDED stride-144B tile images (straight uint4 copy in mlp).
// ---------------------------------------------------------------------------
__global__ __launch_bounds__(128)
void prep_kernel(const float* __restrict__ W1s, const float* __restrict__ b1s,
                 const float* __restrict__ gam, const float* __restrict__ bet,
                 const float* __restrict__ W2s, const float* __restrict__ b2s)
{
    const int l = blockIdx.x;
    const int tid = threadIdx.x;
    const float bns = rsqrtf(1.0f + 1e-5f);
    // iterate over output u32 pairs: n in [0,64), kp in [0,32)
    for (int idx = tid; idx < 64 * 32; idx += 128) {
        int n = idx >> 5, kp = idx & 31;
        int k0 = 2 * kp, k1 = 2 * kp + 1;
        float gs = gam[l * DIM + n] * bns;
        float a0 = W1s[l * DIM * DIM + k0 * DIM + n] * gs;
        float a1 = W1s[l * DIM * DIM + k1 * DIM + n] * gs;
        __nv_bfloat16 h0 = __float2bfloat16(a0), h1 = __float2bfloat16(a1);
        __nv_bfloat16 e0 = __float2bfloat16(a0 - __bfloat162float(h0));
        __nv_bfloat16 e1 = __float2bfloat16(a1 - __bfloat162float(h1));
        g_wbp[l][0][n * 36 + kp] = pbf2(h0, h1);
        g_wbp[l][1][n * 36 + kp] = pbf2(e0, e1);
        float c0 = W2s[l * DIM * DIM + k0 * DIM + n];
        float c1 = W2s[l * DIM * DIM + k1 * DIM + n];
        __nv_bfloat16 h2 = __float2bfloat16(c0), h3 = __float2bfloat16(c1);
        __nv_bfloat16 e2 = __float2bfloat16(c0 - __bfloat162float(h2));
        __nv_bfloat16 e3 = __float2bfloat16(c1 - __bfloat162float(h3));
        g_wbp[l][2][n * 36 + kp] = pbf2(h2, h3);
        g_wbp[l][3][n * 36 + kp] = pbf2(e2, e3);
    }
    if (tid < DIM) {
        g_bias[l][0][tid] = b1s[l * DIM + tid] * (gam[l * DIM + tid] * bns) + bet[l * DIM + tid];
        g_bias[l][1][tid] = b2s[l * DIM + tid];
    }
}

// ---------------------------------------------------------------------------
// Gather aggregate (atomic-free): z[i] = h[i] + sum_{j in N(i)} h[j],
// written pre-split as bf16 hi/lo pair arrays (mlp consumes directly).
// 16 lanes per node (float4 each), 16 nodes per 256-thread block.
// ---------------------------------------------------------------------------
__global__ __launch_bounds__(256)
void gather_kernel(const float* __restrict__ h,
                   uint32_t* __restrict__ zhi, uint32_t* __restrict__ zlo)
{
    const int tid  = threadIdx.x;
    const int lane = tid & 15;
    const int node = blockIdx.x * 16 + (tid >> 4);
    if (node >= NN) return;

    float4 acc = *reinterpret_cast<const float4*>(h + (size_t)node * DIM + lane * 4);
    const int e0 = g_off[node];
    const int e1 = g_off[node + 1];
    for (int e = e0; e < e1; e++) {
        int s = __ldg(&g_ssrc[e]);
        float4 v = *reinterpret_cast<const float4*>(h + (size_t)s * DIM + lane * 4);
        acc.x += v.x; acc.y += v.y; acc.z += v.z; acc.w += v.w;
    }
    __nv_bfloat16 h0 = __float2bfloat16(acc.x), h1 = __float2bfloat16(acc.y);
    __nv_bfloat16 h2 = __float2bfloat16(acc.z), h3 = __float2bfloat16(acc.w);
    __nv_bfloat16 l0 = __float2bfloat16(acc.x - __bfloat162float(h0));
    __nv_bfloat16 l1 = __float2bfloat16(acc.y - __bfloat162float(h1));
    __nv_bfloat16 l2 = __float2bfloat16(acc.z - __bfloat162float(h2));
    __nv_bfloat16 l3 = __float2bfloat16(acc.w - __bfloat162float(h3));
    uint2 vh = make_uint2(pbf2(h0, h1), pbf2(h2, h3));
    uint2 vl = make_uint2(pbf2(l0, l1), pbf2(l2, l3));
    reinterpret_cast<uint2*>(zhi)[(size_t)node * 16 + lane] = vh;
    reinterpret_cast<uint2*>(zlo)[(size_t)node * 16 + lane] = vl;
}

// ---------------------------------------------------------------------------
// Tensor-core MLP via mma.sync bf16 (3-term split, fp32 accum):
//   GEMM1: y = relu((z@W1')+b1'); y written back into the A tiles (own rows)
//   GEMM2: h = relu((y@W2)+b2) -> gmem fp32
// Front phases are pure uint4 copies (z pre-split by gather, W pre-padded).
// 256 threads, 8 warps, 16 rows/warp. W overlay -> 55,808 B -> 4 CTAs/SM.
// ---------------------------------------------------------------------------
#define STR     72                          // bf16 stride (144 B): ldmatrix conflict-free
#define SM_BIAS 0                           // 128 floats = 512 B
#define SM_A0   512                         // 128*72*2 = 18432
#define SM_A1   (SM_A0 + 128 * STR * 2)     // 18944
#define SM_W    (SM_A1 + 128 * STR * 2)     // 37376; 2 tiles x 64*144B (=9216)
#define SMEM_MM (SM_W + 2 * 64 * STR * 2)   // 55808 B

__global__ __launch_bounds__(256)
void mlp_mma_kernel(const uint32_t* __restrict__ zhi,
                    const uint32_t* __restrict__ zlo,
                    const uint32_t* __restrict__ wpad,   // [4][64*36] padded tiles
                    const float* __restrict__ bias,      // [2][64]
                    float* __restrict__ hout)
{
    extern __shared__ char smem[];
    const uint32_t sb = smem_u32(smem);
    const int tid = threadIdx.x, wid = tid >> 5, lane = tid & 31;

    // --- W1 hi/lo pair: straight 18,432 B copy (1152 uint4) ---
    const uint4* wp = reinterpret_cast<const uint4*>(wpad);
    for (int i = tid; i < 1152; i += 256)
        *reinterpret_cast<uint4*>(smem + SM_W + i * 16) = wp[i];
    if (tid < 128) reinterpret_cast<float*>(smem + SM_BIAS)[tid] = bias[tid];

    // --- z tiles: straight copies with stride-144 row padding ---
    {
        const uint4* zh = reinterpret_cast<const uint4*>(zhi + (size_t)blockIdx.x * 128 * 32);
        const uint4* zl = reinterpret_cast<const uint4*>(zlo + (size_t)blockIdx.x * 128 * 32);
        for (int i = tid; i < 1024; i += 256) {
            int row = i >> 3, q = i & 7;           // q: 16B chunk within row
            *reinterpret_cast<uint4*>(smem + SM_A0 + row * 144 + q * 16) = zh[i];
            *reinterpret_cast<uint4*>(smem + SM_A1 + row * 144 + q * 16) = zl[i];
        }
    }
    __syncthreads();
    const float* sbias = reinterpret_cast<const float*>(smem + SM_BIAS);

    const int g  = lane >> 3;        // ldmatrix address group 0..3
    const int ri = lane & 7;
    const int wrow = wid * 16;       // this warp's row base within CTA tile (16 rows)

    float acc[8][4];

    #pragma unroll
    for (int gemm = 0; gemm < 2; gemm++) {
        const uint32_t wbase = sb + SM_W;                         // hi tile (overlaid)
        #pragma unroll
        for (int nt = 0; nt < 8; nt++) {
            int c = nt * 8 + (lane & 3) * 2;
            float b0 = sbias[gemm * 64 + c], b1v = sbias[gemm * 64 + c + 1];
            acc[nt][0] = b0; acc[nt][1] = b1v;
            acc[nt][2] = b0; acc[nt][3] = b1v;
        }

        #pragma unroll
        for (int k = 0; k < 4; k++) {
            const int K = k * 16;
            uint32_t ah[4], al[4];
            {
                uint32_t ao = (uint32_t)((wrow + (g & 1) * 8 + ri) * 144
                                         + (K + (g >> 1) * 8) * 2);
                ldm4(ah, sb + SM_A0 + ao);
                ldm4(al, sb + SM_A1 + ao);
            }
            #pragma unroll
            for (int np = 0; np < 4; np++) {
                uint32_t bo = (uint32_t)((np * 16 + (g >> 1) * 8 + ri) * 144
                                         + (K + (g & 1) * 8) * 2);
                uint32_t bh[4], bl[4];
                ldm4(bh, wbase + bo);
                ldm4(bl, wbase + 9216 + bo);
                #pragma unroll
                for (int h2 = 0; h2 < 2; h2++) {
                    int nt = np * 2 + h2;
                    mma_bf16(acc[nt], ah, bh[2 * h2], bh[2 * h2 + 1]);
                    mma_bf16(acc[nt], ah, bl[2 * h2], bl[2 * h2 + 1]);
                    mma_bf16(acc[nt], al, bh[2 * h2], bh[2 * h2 + 1]);
                }
            }
        }

        if (gemm == 0) {
            // epilogue1: relu, hi/lo split, write back into OWN rows of A tiles
            #pragma unroll
            for (int nt = 0; nt < 8; nt++) {
                int row0 = wrow + (lane >> 2);
                int col  = nt * 8 + (lane & 3) * 2;
                float v0 = fmaxf(acc[nt][0], 0.0f);
                float v1 = fmaxf(acc[nt][1], 0.0f);
                float v2 = fmaxf(acc[nt][2], 0.0f);
                float v3 = fmaxf(acc[nt][3], 0.0f);
                __nv_bfloat16 h0 = __float2bfloat16(v0), h1 = __float2bfloat16(v1);
                __nv_bfloat16 h2 = __float2bfloat16(v2), h3 = __float2bfloat16(v3);
                __nv_bfloat16 e0 = __float2bfloat16(v0 - __bfloat162float(h0));
                __nv_bfloat16 e1 = __float2bfloat16(v1 - __bfloat162float(h1));
                __nv_bfloat16 e2 = __float2bfloat16(v2 - __bfloat162float(h2));
                __nv_bfloat16 e3 = __float2bfloat16(v3 - __bfloat162float(h3));
                uint32_t o0 = (uint32_t)(row0 * 144 + col * 2);
                uint32_t o1 = (uint32_t)((row0 + 8) * 144 + col * 2);
                *reinterpret_cast<uint32_t*>(smem + SM_A0 + o0) = pbf2(h0, h1);
                *reinterpret_cast<uint32_t*>(smem + SM_A0 + o1) = pbf2(h2, h3);
                *reinterpret_cast<uint32_t*>(smem + SM_A1 + o0) = pbf2(e0, e1);
                *reinterpret_cast<uint32_t*>(smem + SM_A1 + o1) = pbf2(e2, e3);
            }
            __syncthreads();          // all warps done reading W1 tiles
            // overlay: W2 hi/lo pair, straight copy
            const uint4* wp2 = wp + 1152;
            for (int i = tid; i < 1152; i += 256)
                *reinterpret_cast<uint4*>(smem + SM_W + i * 16) = wp2[i];
            __syncthreads();          // W2 visible (also covers A-tile writes)
        }
    }

    // epilogue2: relu -> gmem fp32
    {
        const size_t rbase = (size_t)blockIdx.x * 128 + wrow;
        #pragma unroll
        for (int nt = 0; nt < 8; nt++) {
            size_t row0 = rbase + (lane >> 2);
            int col = nt * 8 + (lane & 3) * 2;
            float2 v01 = make_float2(fmaxf(acc[nt][0], 0.0f),
                                     fmaxf(acc[nt][1], 0.0f));
            float2 v23 = make_float2(fmaxf(acc[nt][2], 0.0f),
                                     fmaxf(acc[nt][3], 0.0f));
            *reinterpret_cast<float2*>(hout + row0 * DIM + col)       = v01;
            *reinterpret_cast<float2*>(hout + (row0 + 8) * DIM + col) = v23;
        }
    }
}

// ---------------------------------------------------------------------------
// Global add pool (batch sorted): running segment sums, REDG flush on change.
// Also re-zeroes g_cnt for the next call's histogram (invariant).
// ---------------------------------------------------------------------------
__global__ __launch_bounds__(256)
void pool_kernel(const float* __restrict__ h,
                 const int*   __restrict__ batch,
                 float*       __restrict__ pl)
{
    // restore g_cnt = 0 invariant (grid-strided)
    for (int i = blockIdx.x * blockDim.x + threadIdx.x; i < NN;
         i += gridDim.x * blockDim.x)
        g_cnt[i] = 0;

    const int tid  = threadIdx.x;
    const int lane = tid & 15;
    const int sub  = tid >> 4;
    const int base = blockIdx.x * 1024;

    float4 acc = make_float4(0.f, 0.f, 0.f, 0.f);
    int cur = -1;
    for (int i = 0; i < 64; i++) {
        int n = base + sub + i * 16;
        if (n >= NN) break;
        int g = __ldg(batch + n);
        if (g != cur) {
            if (cur >= 0) {
                float4* a = reinterpret_cast<float4*>(pl + (size_t)cur * DIM + lane * 4);
                asm volatile("red.global.add.v4.f32 [%0], {%1,%2,%3,%4};"
                             :: "l"(a), "f"(acc.x), "f"(acc.y), "f"(acc.z), "f"(acc.w)
                             : "memory");
            }
            cur = g;
            acc = make_float4(0.f, 0.f, 0.f, 0.f);
        }
        float4 v = *reinterpret_cast<const float4*>(h + (size_t)n * DIM + lane * 4);
        acc.x += v.x; acc.y += v.y; acc.z += v.z; acc.w += v.w;
    }
    if (cur >= 0) {
        float4* a = reinterpret_cast<float4*>(pl + (size_t)cur * DIM + lane * 4);
        asm volatile("red.global.add.v4.f32 [%0], {%1,%2,%3,%4};"
                     :: "l"(a), "f"(acc.x), "f"(acc.y), "f"(acc.z), "f"(acc.w)
                     : "memory");
    }
}

// ---------------------------------------------------------------------------
// Final: out = relu(pool @ lin1_w + lin1_b). Zeroes pool after reading.
// ---------------------------------------------------------------------------
__global__ __launch_bounds__(128)
void final_kernel(float*       __restrict__ pl,
                  const float* __restrict__ W,
                  const float* __restrict__ b,
                  float*       __restrict__ out)
{
    extern __shared__ float fsm[];
    float* sW = fsm;              // 4096 floats
    float* sb2 = sW + DIM * DIM;  // 64
    float* sx = sb2 + DIM;        // 64 * 128

    const int tid = threadIdx.x;
    for (int i = tid; i < DIM * DIM; i += 128) sW[i] = W[i];
    if (tid < DIM) sb2[tid] = b[tid];

    float4* pp = reinterpret_cast<float4*>(pl + (size_t)tid * DIM);
    #pragma unroll
    for (int k4 = 0; k4 < 16; k4++) {
        float4 v = pp[k4];
        sx[(4 * k4 + 0) * 128 + tid] = v.x;
        sx[(4 * k4 + 1) * 128 + tid] = v.y;
        sx[(4 * k4 + 2) * 128 + tid] = v.z;
        sx[(4 * k4 + 3) * 128 + tid] = v.w;
        pp[k4] = make_float4(0.f, 0.f, 0.f, 0.f);   // keep pool zeroed
    }
    __syncthreads();

    float acc[DIM];
    #pragma unroll
    for (int j = 0; j < DIM; j++) acc[j] = sb2[j];
    for (int k = 0; k < DIM; k++) {
        float xk = sx[k * 128 + tid];
        #pragma unroll
        for (int j = 0; j < DIM; j += 4) {
            float4 w = *reinterpret_cast<const float4*>(&sW[k * DIM + j]);
            acc[j + 0] += xk * w.x;
            acc[j + 1] += xk * w.y;
            acc[j + 2] += xk * w.z;
            acc[j + 3] += xk * w.w;
        }
    }
    float* op = out + (size_t)tid * DIM;
    #pragma unroll
    for (int j = 0; j < DIM; j++) op[j] = fmaxf(acc[j], 0.0f);
}

// ---------------------------------------------------------------------------
extern "C" void kernel_launch(void* const* d_in, const int* in_sizes, int n_in,
                              void* d_out, int out_size)
{
    const float* x      = (const float*)d_in[0];
    const int*   ei     = (const int*)  d_in[1];
    const int*   batch  = (const int*)  d_in[2];
    const float* W1s    = (const float*)d_in[3];
    const float* b1s    = (const float*)d_in[4];
    const float* gammas = (const float*)d_in[5];
    const float* betas  = (const float*)d_in[6];
    const float* W2s    = (const float*)d_in[7];
    const float* b2s    = (const float*)d_in[8];
    const float* lw     = (const float*)d_in[9];
    const float* lb     = (const float*)d_in[10];
    float* out = (float*)d_out;

    float *hA, *hB, *pl;
    uint32_t *zhi, *zlo, *wbp;
    float* bs;
    cudaGetSymbolAddress((void**)&hA,  g_hA);
    cudaGetSymbolAddress((void**)&hB,  g_hB);
    cudaGetSymbolAddress((void**)&zhi, g_zhi);
    cudaGetSymbolAddress((void**)&zlo, g_zlo);
    cudaGetSymbolAddress((void**)&pl,  g_pool);
    cudaGetSymbolAddress((void**)&wbp, g_wbp);
    cudaGetSymbolAddress((void**)&bs,  g_bias);

    const int final_smem = (DIM * DIM + DIM + DIM * 128) * (int)sizeof(float);
    cudaFuncSetAttribute(mlp_mma_kernel, cudaFuncAttributeMaxDynamicSharedMemorySize, SMEM_MM);
    cudaFuncSetAttribute(final_kernel,   cudaFuncAttributeMaxDynamicSharedMemorySize, final_smem);

    // CSR build + weight prep (g_cnt pre-zeroed by previous call's pool_kernel)
    prep_kernel<<<NL, 128>>>(W1s, b1s, gammas, betas, W2s, b2s);
    hist_kernel<<<(NE + 255) / 256, 256>>>(ei);
    scan1_kernel<<<NBLK, 1024>>>();
    scan2_kernel<<<1, 128>>>();
    scan3_kernel<<<(NN + 255) / 256, 256>>>();
    fill_kernel<<<(NE + 255) / 256, 256>>>(ei);

    const int gat_blocks = (NN + 15) / 16;     // 6250
    const int mlp_blocks = NNP / 128;          // 782

    const float* hcur = x;
    float*       hnxt = hA;
    for (int l = 0; l < NL; l++) {
        gather_kernel<<<gat_blocks, 256>>>(hcur, zhi, zlo);
        mlp_mma_kernel<<<mlp_blocks, 256, SMEM_MM>>>(zhi, zlo,
                                                     wbp + (size_t)l * 4 * 64 * 36,
                                                     bs + (size_t)l * 2 * DIM,
                                                     hnxt);
        hcur = hnxt;
        hnxt = (hcur == hA) ? hB : hA;
    }

    pool_kernel<<<(NN + 1023) / 1024, 256>>>(hcur, batch, pl);
    final_kernel<<<1, 128, final_smem>>>(pl, lw, lb, out);
}

// round 16
// speedup vs baseline: 1.1727x; 1.0344x over previous
#include <cuda_runtime.h>
#include <cuda_bf16.h>
#include <cstdint>

#define NN      100000
#define NNP     100096          // padded to 782*128 rows
#define NE      1200000
#define DIM     64
#define NG      128
#define NL      5
#define NBLK    98              // ceil(NN/1024)

// Persistent scratch (device globals — no allocation). Zero-init at load.
// Invariants: g_pool zeroed by final_kernel; g_cnt zeroed by pool_kernel;
// pad rows [NN,NNP) of g_zhi/g_zlo never written -> stay 0.
__device__ float    g_hA[NNP * DIM];
__device__ float    g_hB[NNP * DIM];
__device__ uint32_t g_zhi[NNP * 32];   // z hi bf16 pairs, 32 u32 per row
__device__ uint32_t g_zlo[NNP * 32];   // z lo bf16 pairs
__device__ float    g_pool[NG * DIM];
__device__ int      g_cnt[NN];
__device__ int      g_off[NN + 1];
__device__ int      g_bsum[128];
__device__ int      g_ssrc[NE];
// Pre-padded weight tiles: [layer][{W1hi,W1lo,W2hi,W2lo}][64 rows x 36 u32]
// (row stride 144 B = ldmatrix-friendly; padding u32s stay 0)
__device__ uint32_t g_wbp[NL][4][64 * 36];
__device__ float    g_bias[NL][2][DIM];

// ---------------------------------------------------------------------------
// warp-MMA helpers (sm_80+ instructions; valid on plain sm_100 target)
// ---------------------------------------------------------------------------
__device__ __forceinline__ uint32_t smem_u32(const void* p) {
    uint32_t a;
    asm("{ .reg .u64 t; cvta.to.shared.u64 t, %1; cvt.u32.u64 %0, t; }"
        : "=r"(a) : "l"(p));
    return a;
}
__device__ __forceinline__ void ldm4(uint32_t* r, uint32_t addr) {
    asm volatile("ldmatrix.sync.aligned.m8n8.x4.shared.b16 {%0,%1,%2,%3}, [%4];"
                 : "=r"(r[0]), "=r"(r[1]), "=r"(r[2]), "=r"(r[3]) : "r"(addr));
}
__device__ __forceinline__ void mma_bf16(float* d, const uint32_t* a,
                                         uint32_t b0, uint32_t b1) {
    asm volatile("mma.sync.aligned.m16n8k16.row.col.f32.bf16.bf16.f32 "
                 "{%0,%1,%2,%3}, {%4,%5,%6,%7}, {%8,%9}, {%0,%1,%2,%3};"
                 : "+f"(d[0]), "+f"(d[1]), "+f"(d[2]), "+f"(d[3])
                 : "r"(a[0]), "r"(a[1]), "r"(a[2]), "r"(a[3]), "r"(b0), "r"(b1));
}
__device__ __forceinline__ uint32_t pbf2(__nv_bfloat16 a, __nv_bfloat16 b) {
    __nv_bfloat162 t(a, b);
    return *reinterpret_cast<uint32_t*>(&t);
}

// ---------------------------------------------------------------------------
// hist + weight prep fused. g_cnt arrives zeroed (load-time init / previous
// call's pool_kernel). Blocks 0..NL-1 additionally prep layer blockIdx.x.
// ---------------------------------------------------------------------------
__global__ __launch_bounds__(256)
void hist_prep_kernel(const int* __restrict__ ei,
                      const float* __restrict__ W1s, const float* __restrict__ b1s,
                      const float* __restrict__ gam, const float* __restrict__ bet,
                      const float* __restrict__ W2s, const float* __restrict__ b2s)
{
    int e = blockIdx.x * blockDim.x + threadIdx.x;
    if (e < NE) atomicAdd(&g_cnt[__ldg(ei + NE + e)], 1);

    if (blockIdx.x < NL) {
        const int l = blockIdx.x;
        const int tid = threadIdx.x;
        const float bns = rsqrtf(1.0f + 1e-5f);
        for (int idx = tid; idx < 64 * 32; idx += 256) {
            int n = idx >> 5, kp = idx & 31;
            int k0 = 2 * kp, k1 = 2 * kp + 1;
            float gs = gam[l * DIM + n] * bns;
            float a0 = W1s[l * DIM * DIM + k0 * DIM + n] * gs;
            float a1 = W1s[l * DIM * DIM + k1 * DIM + n] * gs;
            __nv_bfloat16 h0 = __float2bfloat16(a0), h1 = __float2bfloat16(a1);
            __nv_bfloat16 e0 = __float2bfloat16(a0 - __bfloat162float(h0));
            __nv_bfloat16 e1 = __float2bfloat16(a1 - __bfloat162float(h1));
            g_wbp[l][0][n * 36 + kp] = pbf2(h0, h1);
            g_wbp[l][1][n * 36 + kp] = pbf2(e0, e1);
            float c0 = W2s[l * DIM * DIM + k0 * DIM + n];
            float c1 = W2s[l * DIM * DIM + k1 * DIM + n];
            __nv_bfloat16 h2 = __float2bfloat16(c0), h3 = __float2bfloat16(c1);
            __nv_bfloat16 e2 = __float2bfloat16(c0 - __bfloat162float(h2));
            __nv_bfloat16 e3 = __float2bfloat16(c1 - __bfloat162float(h3));
            g_wbp[l][2][n * 36 + kp] = pbf2(h2, h3);
            g_wbp[l][3][n * 36 + kp] = pbf2(e2, e3);
        }
        if (tid < DIM) {
            g_bias[l][0][tid] = b1s[l * DIM + tid] * (gam[l * DIM + tid] * bns)
                                + bet[l * DIM + tid];
            g_bias[l][1][tid] = b2s[l * DIM + tid];
        }
    }
}

// Phase 1: per-block exclusive scan of 1024 elements + block total.
__global__ __launch_bounds__(1024)
void scan1_kernel() {
    __shared__ int sh[1024];
    const int t = threadIdx.x;
    const int i = blockIdx.x * 1024 + t;
    int v = (i < NN) ? g_cnt[i] : 0;
    sh[t] = v;
    __syncthreads();
    #pragma unroll
    for (int off = 1; off < 1024; off <<= 1) {
        int u = (t >= off) ? sh[t - off] : 0;
        __syncthreads();
        sh[t] += u;
        __syncthreads();
    }
    if (i < NN) g_off[i] = sh[t] - v;              // exclusive within block
    if (t == 1023) g_bsum[blockIdx.x] = sh[1023];  // block total
}

// Phase 2+3 merged: each block redundantly scans the 98 block totals in smem
// (trivial), then applies offsets, mirrors fill cursor, closes the CSR.
__global__ __launch_bounds__(256)
void scan23_kernel() {
    __shared__ int sh[128];
    __shared__ int sex[128];
    const int t = threadIdx.x;
    if (t < 128) {
        int v = (t < NBLK) ? g_bsum[t] : 0;
        sh[t] = v;
        sex[t] = v;          // temp: original value
    }
    __syncthreads();
    #pragma unroll
    for (int off = 1; off < 128; off <<= 1) {
        int u = (t < 128 && t >= off) ? sh[t - off] : 0;
        __syncthreads();
        if (t < 128) sh[t] += u;
        __syncthreads();
    }
    if (t < 128) sex[t] = sh[t] - sex[t];   // exclusive prefix
    __syncthreads();

    int i = blockIdx.x * 256 + t;
    if (i < NN) {
        int o = g_off[i] + sex[i >> 10];
        g_off[i] = o;
        g_cnt[i] = o;        // reuse as fill cursor
    }
    if (i == 0) g_off[NN] = NE;
}

__global__ void fill_kernel(const int* __restrict__ ei) {
    int e = blockIdx.x * blockDim.x + threadIdx.x;
    if (e >= NE) return;
    int d = __ldg(ei + NE + e);
    int pos = atomicAdd(&g_cnt[d], 1);
    g_ssrc[pos] = __ldg(ei + e);
}

// ---------------------------------------------------------------------------
// Gather aggregate (atomic-free): z[i] = h[i] + sum_{j in N(i)} h[j],
// written pre-split as bf16 hi/lo pair arrays (mlp consumes directly).
// 16 lanes per node (float4 each), 16 nodes per 256-thread block.
// ---------------------------------------------------------------------------
__global__ __launch_bounds__(256)
void gather_kernel(const float* __restrict__ h,
                   uint32_t* __restrict__ zhi, uint32_t* __restrict__ zlo)
{
    const int tid  = threadIdx.x;
    const int lane = tid & 15;
    const int node = blockIdx.x * 16 + (tid >> 4);
    if (node >= NN) return;

    float4 acc = *reinterpret_cast<const float4*>(h + (size_t)node * DIM + lane * 4);
    const int e0 = g_off[node];
    const int e1 = g_off[node + 1];
    for (int e = e0; e < e1; e++) {
        int s = __ldg(&g_ssrc[e]);
        float4 v = *reinterpret_cast<const float4*>(h + (size_t)s * DIM + lane * 4);
        acc.x += v.x; acc.y += v.y; acc.z += v.z; acc.w += v.w;
    }
    __nv_bfloat16 h0 = __float2bfloat16(acc.x), h1 = __float2bfloat16(acc.y);
    __nv_bfloat16 h2 = __float2bfloat16(acc.z), h3 = __float2bfloat16(acc.w);
    __nv_bfloat16 l0 = __float2bfloat16(acc.x - __bfloat162float(h0));
    __nv_bfloat16 l1 = __float2bfloat16(acc.y - __bfloat162float(h1));
    __nv_bfloat16 l2 = __float2bfloat16(acc.z - __bfloat162float(h2));
    __nv_bfloat16 l3 = __float2bfloat16(acc.w - __bfloat162float(h3));
    uint2 vh = make_uint2(pbf2(h0, h1), pbf2(h2, h3));
    uint2 vl = make_uint2(pbf2(l0, l1), pbf2(l2, l3));
    reinterpret_cast<uint2*>(zhi)[(size_t)node * 16 + lane] = vh;
    reinterpret_cast<uint2*>(zlo)[(size_t)node * 16 + lane] = vl;
}

// ---------------------------------------------------------------------------
// Tensor-core MLP via mma.sync bf16 (3-term split, fp32 accum):
//   GEMM1: y = relu((z@W1')+b1'); y written back into the A tiles (own rows)
//   GEMM2: h = relu((y@W2)+b2) -> gmem fp32
// Front phases are pure uint4 copies. W2 is PREFETCHED into registers at
// kernel start and dumped to smem after GEMM1 (hides the post-sync L2 read).
// 256 threads, 8 warps, 16 rows/warp. W overlay -> 55,808 B -> 4 CTAs/SM.
// ---------------------------------------------------------------------------
#define STR     72                          // bf16 stride (144 B): ldmatrix conflict-free
#define SM_BIAS 0                           // 128 floats = 512 B
#define SM_A0   512                         // 128*72*2 = 18432
#define SM_A1   (SM_A0 + 128 * STR * 2)     // 18944
#define SM_W    (SM_A1 + 128 * STR * 2)     // 37376; 2 tiles x 64*144B (=9216)
#define SMEM_MM (SM_W + 2 * 64 * STR * 2)   // 55808 B

__global__ __launch_bounds__(256)
void mlp_mma_kernel(const uint32_t* __restrict__ zhi,
                    const uint32_t* __restrict__ zlo,
                    const uint32_t* __restrict__ wpad,   // [4][64*36] padded tiles
                    const float* __restrict__ bias,      // [2][64]
                    float* __restrict__ hout)
{
    extern __shared__ char smem[];
    const uint32_t sb = smem_u32(smem);
    const int tid = threadIdx.x, wid = tid >> 5, lane = tid & 31;

    // --- W1 hi/lo pair: straight 18,432 B copy (1152 uint4) ---
    const uint4* wp = reinterpret_cast<const uint4*>(wpad);
    for (int i = tid; i < 1152; i += 256)
        *reinterpret_cast<uint4*>(smem + SM_W + i * 16) = wp[i];
    if (tid < 128) reinterpret_cast<float*>(smem + SM_BIAS)[tid] = bias[tid];

    // --- prefetch W2 hi/lo pair into registers (dumped post-GEMM1) ---
    uint4 w2r[5];
    const uint4* wp2 = wp + 1152;
    #pragma unroll
    for (int k = 0; k < 5; k++) {
        int i = tid + k * 256;
        if (i < 1152) w2r[k] = wp2[i];
    }

    // --- z tiles: straight copies with stride-144 row padding ---
    {
        const uint4* zh = reinterpret_cast<const uint4*>(zhi + (size_t)blockIdx.x * 128 * 32);
        const uint4* zl = reinterpret_cast<const uint4*>(zlo + (size_t)blockIdx.x * 128 * 32);
        for (int i = tid; i < 1024; i += 256) {
            int row = i >> 3, q = i & 7;           // q: 16B chunk within row
            *reinterpret_cast<uint4*>(smem + SM_A0 + row * 144 + q * 16) = zh[i];
            *reinterpret_cast<uint4*>(smem + SM_A1 + row * 144 + q * 16) = zl[i];
        }
    }
    __syncthreads();
    const float* sbias = reinterpret_cast<const float*>(smem + SM_BIAS);

    const int g  = lane >> 3;        // ldmatrix address group 0..3
    const int ri = lane & 7;
    const int wrow = wid * 16;       // this warp's row base within CTA tile (16 rows)

    float acc[8][4];

    #pragma unroll
    for (int gemm = 0; gemm < 2; gemm++) {
        const uint32_t wbase = sb + SM_W;                         // hi tile (overlaid)
        #pragma unroll
        for (int nt = 0; nt < 8; nt++) {
            int c = nt * 8 + (lane & 3) * 2;
            float b0 = sbias[gemm * 64 + c], b1v = sbias[gemm * 64 + c + 1];
            acc[nt][0] = b0; acc[nt][1] = b1v;
            acc[nt][2] = b0; acc[nt][3] = b1v;
        }

        #pragma unroll
        for (int k = 0; k < 4; k++) {
            const int K = k * 16;
            uint32_t ah[4], al[4];
            {
                uint32_t ao = (uint32_t)((wrow + (g & 1) * 8 + ri) * 144
                                         + (K + (g >> 1) * 8) * 2);
                ldm4(ah, sb + SM_A0 + ao);
                ldm4(al, sb + SM_A1 + ao);
            }
            #pragma unroll
            for (int np = 0; np < 4; np++) {
                uint32_t bo = (uint32_t)((np * 16 + (g >> 1) * 8 + ri) * 144
                                         + (K + (g & 1) * 8) * 2);
                uint32_t bh[4], bl[4];
                ldm4(bh, wbase + bo);
                ldm4(bl, wbase + 9216 + bo);
                #pragma unroll
                for (int h2 = 0; h2 < 2; h2++) {
                    int nt = np * 2 + h2;
                    mma_bf16(acc[nt], ah, bh[2 * h2], bh[2 * h2 + 1]);
                    mma_bf16(acc[nt], ah, bl[2 * h2], bl[2 * h2 + 1]);
                    mma_bf16(acc[nt], al, bh[2 * h2], bh[2 * h2 + 1]);
                }
            }
        }

        if (gemm == 0) {
            // epilogue1: relu, hi/lo split, write back into OWN rows of A tiles
            #pragma unroll
            for (int nt = 0; nt < 8; nt++) {
                int row0 = wrow + (lane >> 2);
                int col  = nt * 8 + (lane & 3) * 2;
                float v0 = fmaxf(acc[nt][0], 0.0f);
                float v1 = fmaxf(acc[nt][1], 0.0f);
                float v2 = fmaxf(acc[nt][2], 0.0f);
                float v3 = fmaxf(acc[nt][3], 0.0f);
                __nv_bfloat16 h0 = __float2bfloat16(v0), h1 = __float2bfloat16(v1);
                __nv_bfloat16 h2 = __float2bfloat16(v2), h3 = __float2bfloat16(v3);
                __nv_bfloat16 e0 = __float2bfloat16(v0 - __bfloat162float(h0));
                __nv_bfloat16 e1 = __float2bfloat16(v1 - __bfloat162float(h1));
                __nv_bfloat16 e2 = __float2bfloat16(v2 - __bfloat162float(h2));
                __nv_bfloat16 e3 = __float2bfloat16(v3 - __bfloat162float(h3));
                uint32_t o0 = (uint32_t)(row0 * 144 + col * 2);
                uint32_t o1 = (uint32_t)((row0 + 8) * 144 + col * 2);
                *reinterpret_cast<uint32_t*>(smem + SM_A0 + o0) = pbf2(h0, h1);
                *reinterpret_cast<uint32_t*>(smem + SM_A0 + o1) = pbf2(h2, h3);
                *reinterpret_cast<uint32_t*>(smem + SM_A1 + o0) = pbf2(e0, e1);
                *reinterpret_cast<uint32_t*>(smem + SM_A1 + o1) = pbf2(e2, e3);
            }
            __syncthreads();          // all warps done reading W1 tiles
            // overlay: W2 hi/lo pair from prefetched registers
            #pragma unroll
            for (int k = 0; k < 5; k++) {
                int i = tid + k * 256;
                if (i < 1152)
                    *reinterpret_cast<uint4*>(smem + SM_W + i * 16) = w2r[k];
            }
            __syncthreads();          // W2 visible (also covers A-tile writes)
        }
    }

    // epilogue2: relu -> gmem fp32
    {
        const size_t rbase = (size_t)blockIdx.x * 128 + wrow;
        #pragma unroll
        for (int nt = 0; nt < 8; nt++) {
            size_t row0 = rbase + (lane >> 2);
            int col = nt * 8 + (lane & 3) * 2;
            float2 v01 = make_float2(fmaxf(acc[nt][0], 0.0f),
                                     fmaxf(acc[nt][1], 0.0f));
            float2 v23 = make_float2(fmaxf(acc[nt][2], 0.0f),
                                     fmaxf(acc[nt][3], 0.0f));
            *reinterpret_cast<float2*>(hout + row0 * DIM + col)       = v01;
            *reinterpret_cast<float2*>(hout + (row0 + 8) * DIM + col) = v23;
        }
    }
}

// ---------------------------------------------------------------------------
// Global add pool (batch sorted): running segment sums, REDG flush on change.
// Also re-zeroes g_cnt for the next call's histogram (invariant).
// ---------------------------------------------------------------------------
__global__ __launch_bounds__(256)
void pool_kernel(const float* __restrict__ h,
                 const int*   __restrict__ batch,
                 float*       __restrict__ pl)
{
    // restore g_cnt = 0 invariant (grid-strided)
    for (int i = blockIdx.x * blockDim.x + threadIdx.x; i < NN;
         i += gridDim.x * blockDim.x)
        g_cnt[i] = 0;

    const int tid  = threadIdx.x;
    const int lane = tid & 15;
    const int sub  = tid >> 4;
    const int base = blockIdx.x * 1024;

    float4 acc = make_float4(0.f, 0.f, 0.f, 0.f);
    int cur = -1;
    for (int i = 0; i < 64; i++) {
        int n = base + sub + i * 16;
        if (n >= NN) break;
        int g = __ldg(batch + n);
        if (g != cur) {
            if (cur >= 0) {
                float4* a = reinterpret_cast<float4*>(pl + (size_t)cur * DIM + lane * 4);
                asm volatile("red.global.add.v4.f32 [%0], {%1,%2,%3,%4};"
                             :: "l"(a), "f"(acc.x), "f"(acc.y), "f"(acc.z), "f"(acc.w)
                             : "memory");
            }
            cur = g;
            acc = make_float4(0.f, 0.f, 0.f, 0.f);
        }
        float4 v = *reinterpret_cast<const float4*>(h + (size_t)n * DIM + lane * 4);
        acc.x += v.x; acc.y += v.y; acc.z += v.z; acc.w += v.w;
    }
    if (cur >= 0) {
        float4* a = reinterpret_cast<float4*>(pl + (size_t)cur * DIM + lane * 4);
        asm volatile("red.global.add.v4.f32 [%0], {%1,%2,%3,%4};"
                     :: "l"(a), "f"(acc.x), "f"(acc.y), "f"(acc.z), "f"(acc.w)
                     : "memory");
    }
}

// ---------------------------------------------------------------------------
// Final: out = relu(pool @ lin1_w + lin1_b). Zeroes pool after reading.
// ---------------------------------------------------------------------------
__global__ __launch_bounds__(128)
void final_kernel(float*       __restrict__ pl,
                  const float* __restrict__ W,
                  const float* __restrict__ b,
                  float*       __restrict__ out)
{
    extern __shared__ float fsm[];
    float* sW = fsm;              // 4096 floats
    float* sb2 = sW + DIM * DIM;  // 64
    float* sx = sb2 + DIM;        // 64 * 128

    const int tid = threadIdx.x;
    for (int i = tid; i < DIM * DIM; i += 128) sW[i] = W[i];
    if (tid < DIM) sb2[tid] = b[tid];

    float4* pp = reinterpret_cast<float4*>(pl + (size_t)tid * DIM);
    #pragma unroll
    for (int k4 = 0; k4 < 16; k4++) {
        float4 v = pp[k4];
        sx[(4 * k4 + 0) * 128 + tid] = v.x;
        sx[(4 * k4 + 1) * 128 + tid] = v.y;
        sx[(4 * k4 + 2) * 128 + tid] = v.z;
        sx[(4 * k4 + 3) * 128 + tid] = v.w;
        pp[k4] = make_float4(0.f, 0.f, 0.f, 0.f);   // keep pool zeroed
    }
    __syncthreads();

    float acc[DIM];
    #pragma unroll
    for (int j = 0; j < DIM; j++) acc[j] = sb2[j];
    for (int k = 0; k < DIM; k++) {
        float xk = sx[k * 128 + tid];
        #pragma unroll
        for (int j = 0; j < DIM; j += 4) {
            float4 w = *reinterpret_cast<const float4*>(&sW[k * DIM + j]);
            acc[j + 0] += xk * w.x;
            acc[j + 1] += xk * w.y;
            acc[j + 2] += xk * w.z;
            acc[j + 3] += xk * w.w;
        }
    }
    float* op = out + (size_t)tid * DIM;
    #pragma unroll
    for (int j = 0; j < DIM; j++) op[j] = fmaxf(acc[j], 0.0f);
}

// ---------------------------------------------------------------------------
extern "C" void kernel_launch(void* const* d_in, const int* in_sizes, int n_in,
                              void* d_out, int out_size)
{
    const float* x      = (const float*)d_in[0];
    const int*   ei     = (const int*)  d_in[1];
    const int*   batch  = (const int*)  d_in[2];
    const float* W1s    = (const float*)d_in[3];
    const float* b1s    = (const float*)d_in[4];
    const float* gammas = (const float*)d_in[5];
    const float* betas  = (const float*)d_in[6];
    const float* W2s    = (const float*)d_in[7];
    const float* b2s    = (const float*)d_in[8];
    const float* lw     = (const float*)d_in[9];
    const float* lb     = (const float*)d_in[10];
    float* out = (float*)d_out;

    float *hA, *hB, *pl;
    uint32_t *zhi, *zlo, *wbp;
    float* bs;
    cudaGetSymbolAddress((void**)&hA,  g_hA);
    cudaGetSymbolAddress((void**)&hB,  g_hB);
    cudaGetSymbolAddress((void**)&zhi, g_zhi);
    cudaGetSymbolAddress((void**)&zlo, g_zlo);
    cudaGetSymbolAddress((void**)&pl,  g_pool);
    cudaGetSymbolAddress((void**)&wbp, g_wbp);
    cudaGetSymbolAddress((void**)&bs,  g_bias);

    const int final_smem = (DIM * DIM + DIM + DIM * 128) * (int)sizeof(float);
    cudaFuncSetAttribute(mlp_mma_kernel, cudaFuncAttributeMaxDynamicSharedMemorySize, SMEM_MM);
    cudaFuncSetAttribute(final_kernel,   cudaFuncAttributeMaxDynamicSharedMemorySize, final_smem);

    // CSR build + weight prep (g_cnt pre-zeroed by previous call's pool_kernel)
    hist_prep_kernel<<<(NE + 255) / 256, 256>>>(ei, W1s, b1s, gammas, betas, W2s, b2s);
    scan1_kernel<<<NBLK, 1024>>>();
    scan23_kernel<<<(NN + 255) / 256, 256>>>();
    fill_kernel<<<(NE + 255) / 256, 256>>>(ei);

    const int gat_blocks = (NN + 15) / 16;     // 6250
    const int mlp_blocks = NNP / 128;          // 782

    const float* hcur = x;
    float*       hnxt = hA;
    for (int l = 0; l < NL; l++) {
        gather_kernel<<<gat_blocks, 256>>>(hcur, zhi, zlo);
        mlp_mma_kernel<<<mlp_blocks, 256, SMEM_MM>>>(zhi, zlo,
                                                     wbp + (size_t)l * 4 * 64 * 36,
                                                     bs + (size_t)l * 2 * DIM,
                                                     hnxt);
        hcur = hnxt;
        hnxt = (hcur == hA) ? hB : hA;
    }

    pool_kernel<<<(NN + 1023) / 1024, 256>>>(hcur, batch, pl);
    final_kernel<<<1, 128, final_smem>>>(pl, lw, lb, out);
}